// round 9
// baseline (speedup 1.0000x reference)
#include <cuda_runtime.h>

// BottomUp_57131654972209: adding-doubling radiative transfer, v3.
// a,r,t,s : (E,60,48) fp32 -> flux_up, flux_down, absorbed : (E,59,48).
//
// One CTA (384 thr) per TWO atmospheres (96 columns). Each thread owns
// (column g of atm0, column g of atm1) x ~8 layers -> 2x ILP in every
// serial chain. rs obtained per segment via a contracting halo descent
// (12 redundant layers; threads near the bottom are exact) -- no Mobius
// matrices, no rs shfl scan. Upward/downward fluxes remain exact affine
// shfl scans (width 8). Outputs alias input smem buffers with a freeing
// order: down-emit (frees T,S; flux_down->T, a*ww*fd->S), then up-emit
// (frees R; flux_up->R, absorbed = S + a*fu -> S).
// 1/(1+-tmp) division-free via series for 1/(1-tmp^2), tmp<=~0.21.

#define LAY   60
#define LM1   59
#define NC    48
#define BLK   384
#define PITCH 100
#define HALO  12
#define BUFN  6024          // swz(59,95)+1

__device__ __forceinline__ int swz(int l, int c) {
    return l * PITCH + ((l >> 3) << 2) + c;
}
__device__ __forceinline__ float inv3(float u) {   // 1/(1-u), 0<=u<~0.09
    return fmaf(u, fmaf(u, fmaf(u, fmaf(u, 1.0f, 1.0f), 1.0f), 1.0f), 1.0f);
}

__global__ void __launch_bounds__(BLK, 2)
adk(const float* __restrict__ A, const float* __restrict__ R,
    const float* __restrict__ T, const float* __restrict__ S,
    float* __restrict__ Fup, float* __restrict__ Fdn, float* __restrict__ Abs)
{
    extern __shared__ float sm[];
    float* Rs = sm;                 // inputs r   -> later flux_up
    float* Ts = Rs + BUFN;          // inputs t   -> later flux_down
    float* Ss = Ts + BUFN;          // inputs s   -> later absorbed
    float* As = Ss + BUFN;          // inputs a   (stays)

    const int  tid = threadIdx.x;
    const long e0  = (long)blockIdx.x * 2;
    const long ib  = e0 * (LAY * NC);

    // ---- stage 2 atmospheres: 5760 elements, 15 iters, coalesced ----
    #pragma unroll
    for (int k = 0; k < 15; ++k) {
        int i   = tid + k * BLK;
        int atm = i / 2880;
        int rem = i - atm * 2880;
        int l   = rem / NC;
        int c   = rem - l * NC;
        int d   = swz(l, atm * NC + c);
        Rs[d] = R[ib + i];
        Ts[d] = T[ib + i];
        Ss[d] = S[ib + i];
        As[d] = A[ib + i];
    }
    __syncthreads();

    const int j    = tid & 7;              // segment index
    const int gg   = tid >> 3;             // 0..47
    const int c0   = gg;                   // atm0 column
    const int c1   = gg + NC;              // atm1 column
    const int lo   = j * 8;
    const int nv   = (j == 7) ? 3 : 8;
    const int hi   = lo + nv - 1;
    const int base = j * (8 * PITCH + 4) + c0;   // swz(lo, c0); +NC for col1

    // ---- rs via halo descent (exact for j>=5, seeded+contracted for j<=4) ----
    float x0, x1;
    int l0;
    if (hi + HALO >= 58) {
        float ra = Rs[swz(59, c0)], ta = Ts[swz(59, c0)];
        float rb = Rs[swz(59, c1)], tb = Ts[swz(59, c1)];
        x0 = fmaf(ra * ta, ta, ra) * inv3(ra * ra);   // exact rs_body[59]
        x1 = fmaf(rb * tb, tb, rb) * inv3(rb * rb);
        l0 = 58;
    } else {
        x0 = 0.18f; x1 = 0.18f;                        // seed; error decays ~0.17^12
        l0 = hi + HALO;
    }
    for (int l = l0; l > hi; --l) {
        int d = swz(l, c0);
        float ra = Rs[d],      ta = Ts[d];
        float rb = Rs[d + NC], tb = Ts[d + NC];
        float p0 = x0 * ra,    p1 = x1 * rb;
        float m0 = (1.0f + p0) * inv3(p0 * p0);
        float m1 = (1.0f + p1) * inv3(p1 * p1);
        x0 = fmaf(x0, ta * ta, ra) * m0;
        x1 = fmaf(x1, tb * tb, rb) * m1;
    }

    // ---- owned descent: store rsv + upward (ss,kk); build both affine maps ----
    float rsv0[8], rsv1[8], ssu0[8], ssu1[8], kku0[8], kku1[8];
    float amU0 = 1.f, abU0 = 0.f, amU1 = 1.f, abU1 = 0.f;
    float amD0 = 1.f, abD0 = 0.f, amD1 = 1.f, abD1 = 0.f;
    float sn0 = Ss[swz(hi + 1, c0)];
    float sn1 = Ss[swz(hi + 1, c1)];
    #pragma unroll
    for (int i = 7; i >= 0; --i) {
        if (i < nv) {
            int d0 = base + PITCH * i;
            float ra = Rs[d0],      ta = Ts[d0],      sa = Ss[d0];
            float rb = Rs[d0 + NC], tb = Ts[d0 + NC], sb = Ss[d0 + NC];
            float s1a = sn0; sn0 = sa;
            float s1b = sn1; sn1 = sb;
            {   // col 0
                float rv  = x0;            rsv0[i] = rv;
                float tmp = rv * ra;
                float iv  = inv3(tmp * tmp);
                float i1p = (1.0f - tmp) * iv;
                float i1m = (1.0f + tmp) * iv;
                float sU  = fmaf(s1a, fmaf(tmp, i1p, 1.0f), sa * rv * i1p);
                float kU  = ta * i1m;
                ssu0[i] = sU; kku0[i] = kU;
                amU0 = kU * amU0;
                abU0 = kU * (abU0 + sU);
                float sD  = fmaf(sa, fmaf(tmp, i1m, 1.0f), s1a * ra * i1m);
                float kD  = ta * i1p;
                float w   = amD0 * kD;
                abD0 = fmaf(w, sD, abD0);
                amD0 = w;
                x0 = fmaf(rv, ta * ta, ra) * i1m;
            }
            {   // col 1
                float rv  = x1;            rsv1[i] = rv;
                float tmp = rv * rb;
                float iv  = inv3(tmp * tmp);
                float i1p = (1.0f - tmp) * iv;
                float i1m = (1.0f + tmp) * iv;
                float sU  = fmaf(s1b, fmaf(tmp, i1p, 1.0f), sb * rv * i1p);
                float kU  = tb * i1m;
                ssu1[i] = sU; kku1[i] = kU;
                amU1 = kU * amU1;
                abU1 = kU * (abU1 + sU);
                float sD  = fmaf(sb, fmaf(tmp, i1m, 1.0f), s1b * rb * i1m);
                float kD  = tb * i1p;
                float w   = amD1 * kD;
                abD1 = fmaf(w, sD, abD1);
                amD1 = w;
                x1 = fmaf(rv, tb * tb, rb) * i1m;
            }
        }
    }

    // ---- upward suffix scan + downward prefix scan (affine, width 8) ----
    #pragma unroll
    for (int d = 1; d < 8; d <<= 1) {
        float fm0 = __shfl_down_sync(0xffffffffu, amU0, d, 8);
        float fb0 = __shfl_down_sync(0xffffffffu, abU0, d, 8);
        float fm1 = __shfl_down_sync(0xffffffffu, amU1, d, 8);
        float fb1 = __shfl_down_sync(0xffffffffu, abU1, d, 8);
        float gm0 = __shfl_up_sync  (0xffffffffu, amD0, d, 8);
        float gb0 = __shfl_up_sync  (0xffffffffu, abD0, d, 8);
        float gm1 = __shfl_up_sync  (0xffffffffu, amD1, d, 8);
        float gb1 = __shfl_up_sync  (0xffffffffu, abD1, d, 8);
        if (j + d < 8) {
            abU0 = fmaf(amU0, fb0, abU0); amU0 *= fm0;
            abU1 = fmaf(amU1, fb1, abU1); amU1 *= fm1;
        }
        if (j >= d) {
            abD0 = fmaf(amD0, gb0, abD0); amD0 *= gm0;
            abD1 = fmaf(amD1, gb1, abD1); amD1 *= gm1;
        }
    }
    float cu0 = __shfl_down_sync(0xffffffffu, abU0, 1, 8);
    float cu1 = __shfl_down_sync(0xffffffffu, abU1, 1, 8);
    float cd0 = __shfl_up_sync  (0xffffffffu, abD0, 1, 8);
    float cd1 = __shfl_up_sync  (0xffffffffu, abD1, 1, 8);
    cu0 = (j == 7) ? 0.0f : cu0;
    cu1 = (j == 7) ? 0.0f : cu1;
    cd0 = (j == 0) ? 0.0f : cd0;
    cd1 = (j == 0) ? 0.0f : cd1;

    // boundary s[hi+1] (neighbor-owned) BEFORE any smem writes, then fence
    float stp0 = Ss[swz(hi + 1, c0)];
    float stp1 = Ss[swz(hi + 1, c1)];
    __syncwarp();

    // ---- down-emit (ascending): flux_down -> Ts,  a*ww*fd -> Ss ----
    float sc0 = Ss[base], sc1 = Ss[base + NC];   // s[lo]
    #pragma unroll
    for (int i = 0; i < 8; ++i) {
        if (i < nv) {
            int d0 = base + PITCH * i;
            float s1a = (i == nv - 1) ? stp0 : Ss[d0 + PITCH];
            float s1b = (i == nv - 1) ? stp1 : Ss[d0 + PITCH + NC];
            {   // col 0
                float ra = Rs[d0], ta = Ts[d0], aa = As[d0];
                float rv  = rsv0[i];
                float tmp = rv * ra;
                float iv  = inv3(tmp * tmp);
                float i1p = (1.0f - tmp) * iv;
                float i1m = (1.0f + tmp) * iv;
                float sD  = fmaf(sc0, fmaf(tmp, i1m, 1.0f), s1a * ra * i1m);
                float ww  = fmaf(ta * rv, i1p, 1.0f);
                float fd  = cd0 + sD;
                Ts[d0] = fd;                       // t[l] already consumed
                Ss[d0] = aa * ww * fd;             // abs partial
                cd0 = fd * (ta * i1p);
                sc0 = s1a;
            }
            {   // col 1
                float rb = Rs[d0 + NC], tb = Ts[d0 + NC], ab_ = As[d0 + NC];
                float rv  = rsv1[i];
                float tmp = rv * rb;
                float iv  = inv3(tmp * tmp);
                float i1p = (1.0f - tmp) * iv;
                float i1m = (1.0f + tmp) * iv;
                float sD  = fmaf(sc1, fmaf(tmp, i1m, 1.0f), s1b * rb * i1m);
                float ww  = fmaf(tb * rv, i1p, 1.0f);
                float fd  = cd1 + sD;
                Ts[d0 + NC] = fd;
                Ss[d0 + NC] = ab_ * ww * fd;
                cd1 = fd * (tb * i1p);
                sc1 = s1b;
            }
        }
    }

    // ---- up-emit (descending): flux_up -> Rs,  absorbed -> Ss ----
    #pragma unroll
    for (int i = 7; i >= 0; --i) {
        if (i < nv) {
            int d0 = base + PITCH * i;
            {
                float fu = cu0 + ssu0[i];
                cu0 = fu * kku0[i];
                float aa = As[d0];
                float p  = Ss[d0];
                Rs[d0] = fu;                        // r[l] dead after down-emit
                Ss[d0] = fmaf(aa, fu, p);           // absorbed
            }
            {
                float fu = cu1 + ssu1[i];
                cu1 = fu * kku1[i];
                float aa = As[d0 + NC];
                float p  = Ss[d0 + NC];
                Rs[d0 + NC] = fu;
                Ss[d0 + NC] = fmaf(aa, fu, p);
            }
        }
    }

    // ---- writeback (coalesced): 5664 elements ----
    __syncthreads();
    const long ob = e0 * (LM1 * NC);
    #pragma unroll
    for (int k = 0; k < 15; ++k) {
        int i = tid + k * BLK;
        if (i < 2 * LM1 * NC) {
            int atm = i / 2832;
            int rem = i - atm * 2832;
            int l   = rem / NC;
            int c   = rem - l * NC;
            int d   = swz(l, atm * NC + c);
            Fup[ob + i] = Rs[d];
            Fdn[ob + i] = Ts[d];
            Abs[ob + i] = Ss[d];
        }
    }
}

extern "C" void kernel_launch(void* const* d_in, const int* in_sizes, int n_in,
                              void* d_out, int out_size)
{
    const float* A = (const float*)d_in[0];
    const float* R = (const float*)d_in[1];
    const float* T = (const float*)d_in[2];
    const float* S = (const float*)d_in[3];

    const int total = in_sizes[0];            // E * 60 * 48
    const int E     = total / (LAY * NC);     // 8192 (even)
    const int nper  = E * LM1 * NC;

    float* out  = (float*)d_out;
    float* fup  = out;
    float* fdn  = out + nper;
    float* absd = out + 2 * nper;

    const int smem_bytes = 4 * BUFN * (int)sizeof(float);   // 96,384 B
    cudaFuncSetAttribute(adk, cudaFuncAttributeMaxDynamicSharedMemorySize, smem_bytes);
    adk<<<E / 2, BLK, smem_bytes>>>(A, R, T, S, fup, fdn, absd);
}